// round 2
// baseline (speedup 1.0000x reference)
#include <cuda_runtime.h>

#define B_ 4
#define C_ 64
#define N_ 6400
#define NTILES 100   // N_/64

// ---------------- scratch (device globals; no allocation allowed) ----------
__device__ float g_theta[B_*C_*N_];   // [B][C][N]
__device__ float g_phi  [B_*C_*N_];   // [B][C][N]
__device__ float g_gv   [B_*C_*N_];   // [B][C][N]
__device__ float g_y    [B_*C_*N_];   // [B][C][N]
__device__ float g_Wy   [B_*C_*N_];   // [B][C][N]
__device__ float g_stats[2*C_];       // per-channel sum, sumsq
__device__ float g_sc   [2*C_];       // per-channel scale, shift

// ---------------- f32x2 packed-math helpers (sm_100+) ----------------------
__device__ __forceinline__ unsigned long long pk2(float lo, float hi) {
    unsigned long long r;
    asm("mov.b64 %0, {%1, %2};" : "=l"(r)
        : "r"(__float_as_uint(lo)), "r"(__float_as_uint(hi)));
    return r;
}
__device__ __forceinline__ void upk2(unsigned long long v, float &lo, float &hi) {
    unsigned int a, b;
    asm("mov.b64 {%0, %1}, %2;" : "=r"(a), "=r"(b) : "l"(v));
    lo = __uint_as_float(a);
    hi = __uint_as_float(b);
}
__device__ __forceinline__ void fma2(unsigned long long &d,
                                     unsigned long long a, unsigned long long b) {
    asm("fma.rn.f32x2 %0, %1, %2, %0;" : "+l"(d) : "l"(a), "l"(b));
}
__device__ __forceinline__ void mul2(unsigned long long &d, unsigned long long a) {
    asm("mul.rn.f32x2 %0, %1, %0;" : "+l"(d) : "l"(a));
}

// ---------------- kernel 1: fused theta/phi/g projections ------------------
// out[b][o][n] = sum_c x[b][c][n] * w[o][c] + bias[o], for 3 weight sets.
__global__ __launch_bounds__(256) void proj3_kernel(
    const float* __restrict__ x,
    const float* __restrict__ wt, const float* __restrict__ bt,
    const float* __restrict__ wp, const float* __restrict__ bp,
    const float* __restrict__ wg, const float* __restrict__ bg)
{
    __shared__ __align__(16) float xs[64*68];  // xs[c][n]
    __shared__ __align__(16) float ws[64*68];  // ws[c][o] (transposed weights)
    const int b  = blockIdx.y;
    const int n0 = blockIdx.x * 64;
    const int t  = threadIdx.x;
    const int tx = t & 15, ty = t >> 4;

    // zero the BN stats accumulator once per launch (stream-ordered before convW)
    if (blockIdx.x == 0 && b == 0 && t < 128) g_stats[t] = 0.f;

    for (int i = t; i < 4096; i += 256) {
        int c = i >> 6, n = i & 63;
        xs[c*68 + n] = x[((size_t)b*64 + c)*6400 + n0 + n];
    }

    const float* W[3]  = {wt, wp, wg};
    const float* BV[3] = {bt, bp, bg};
    float* OUT[3]      = {g_theta, g_phi, g_gv};

    for (int m = 0; m < 3; m++) {
        __syncthreads();   // first iter: xs done; later: ws reads done
        for (int i = t; i < 4096; i += 256) {
            int o = i >> 6, c = i & 63;
            ws[c*68 + o] = W[m][i];
        }
        __syncthreads();

        float acc[4][4];
        #pragma unroll
        for (int j = 0; j < 4; j++) {
            float bb = BV[m][4*tx + j];
            #pragma unroll
            for (int r = 0; r < 4; r++) acc[r][j] = bb;
        }
        #pragma unroll 4
        for (int c = 0; c < 64; c++) {
            float4 a  = *(const float4*)&xs[c*68 + 4*ty];
            float4 w4 = *(const float4*)&ws[c*68 + 4*tx];
            acc[0][0] += a.x*w4.x; acc[0][1] += a.x*w4.y; acc[0][2] += a.x*w4.z; acc[0][3] += a.x*w4.w;
            acc[1][0] += a.y*w4.x; acc[1][1] += a.y*w4.y; acc[1][2] += a.y*w4.z; acc[1][3] += a.y*w4.w;
            acc[2][0] += a.z*w4.x; acc[2][1] += a.z*w4.y; acc[2][2] += a.z*w4.z; acc[2][3] += a.z*w4.w;
            acc[3][0] += a.w*w4.x; acc[3][1] += a.w*w4.y; acc[3][2] += a.w*w4.z; acc[3][3] += a.w*w4.w;
        }
        float* dst = OUT[m] + (size_t)b*64*6400;
        #pragma unroll
        for (int j = 0; j < 4; j++) {
            float4 v = make_float4(acc[0][j], acc[1][j], acc[2][j], acc[3][j]);
            *(float4*)&dst[(4*tx + j)*6400 + n0 + 4*ty] = v;
        }
    }
}

// ---------------- kernel 2: fused flash attention (fp32, f32x2 FMA) --------
__global__ __launch_bounds__(256, 3) void flash_kernel()
{
    __shared__ __align__(16) float Qt[64*64];  // Qt[c][n]
    __shared__ __align__(16) float KP[64*64];  // K[c][m], later P[n][m]
    __shared__ __align__(16) float Vs[64*64];  // V[m][c] xor-swizzled

    const int b  = blockIdx.y;
    const int n0 = blockIdx.x * 64;
    const int t  = threadIdx.x;
    const int tx = t & 15, ty = t >> 4;

    const float* th = g_theta + (size_t)b*64*6400;
    const float* ph = g_phi   + (size_t)b*64*6400;
    const float* gv = g_gv    + (size_t)b*64*6400;

    for (int i = t; i < 4096; i += 256) {
        int c = i >> 6, n = i & 63;
        Qt[c*64 + n] = th[c*6400 + n0 + n];
    }

    unsigned long long O2[4][2];
    #pragma unroll
    for (int r = 0; r < 4; r++) { O2[r][0] = 0ull; O2[r][1] = 0ull; }
    float mi[4], li[4];
    #pragma unroll
    for (int r = 0; r < 4; r++) { mi[r] = -1e30f; li[r] = 0.f; }

    for (int m0 = 0; m0 < 6400; m0 += 64) {
        __syncthreads();   // previous PV reads of KP/Vs complete
        for (int i = t; i < 4096; i += 256) {
            int c = i >> 6, mm = i & 63;
            float kv = ph[c*6400 + m0 + mm];
            float vv = gv[c*6400 + m0 + mm];
            KP[c*64 + mm] = kv;
            Vs[mm*64 + (c ^ ((mm & 15) << 2))] = vv;   // transpose+swizzle
        }
        __syncthreads();

        // --- S = Q Kᵀ (rank-1 updates over c, packed f32x2) ---
        unsigned long long S2[4][2];
        #pragma unroll
        for (int r = 0; r < 4; r++) { S2[r][0] = 0ull; S2[r][1] = 0ull; }
        #pragma unroll 4
        for (int c = 0; c < 64; c++) {
            ulonglong2 bq = *(const ulonglong2*)&KP[c*64 + 4*tx];
            float4 av = *(const float4*)&Qt[c*64 + 4*ty];
            unsigned long long a0 = pk2(av.x, av.x);
            unsigned long long a1 = pk2(av.y, av.y);
            unsigned long long a2 = pk2(av.z, av.z);
            unsigned long long a3 = pk2(av.w, av.w);
            fma2(S2[0][0], a0, bq.x); fma2(S2[0][1], a0, bq.y);
            fma2(S2[1][0], a1, bq.x); fma2(S2[1][1], a1, bq.y);
            fma2(S2[2][0], a2, bq.x); fma2(S2[2][1], a2, bq.y);
            fma2(S2[3][0], a3, bq.x); fma2(S2[3][1], a3, bq.y);
        }

        // --- online softmax (rows owned by 16-lane tx groups) ---
        float S[4][4], P[4][4];
        #pragma unroll
        for (int r = 0; r < 4; r++) {
            upk2(S2[r][0], S[r][0], S[r][1]);
            upk2(S2[r][1], S[r][2], S[r][3]);
        }
        #pragma unroll
        for (int r = 0; r < 4; r++) {
            float mx = fmaxf(fmaxf(S[r][0], S[r][1]), fmaxf(S[r][2], S[r][3]));
            #pragma unroll
            for (int o = 1; o < 16; o <<= 1)
                mx = fmaxf(mx, __shfl_xor_sync(0xffffffffu, mx, o));
            float mn = fmaxf(mi[r], mx);
            float s = 0.f;
            #pragma unroll
            for (int j = 0; j < 4; j++) {
                P[r][j] = __expf(S[r][j] - mn);
                s += P[r][j];
            }
            #pragma unroll
            for (int o = 1; o < 16; o <<= 1)
                s += __shfl_xor_sync(0xffffffffu, s, o);
            float alpha = __expf(mi[r] - mn);
            li[r] = li[r]*alpha + s;
            mi[r] = mn;
            unsigned long long ad = pk2(alpha, alpha);
            mul2(O2[r][0], ad);
            mul2(O2[r][1], ad);
        }

        __syncthreads();   // all S-GEMM reads of K done before P overwrite
        #pragma unroll
        for (int r = 0; r < 4; r++)
            *(float4*)&KP[(4*ty + r)*64 + 4*tx] =
                make_float4(P[r][0], P[r][1], P[r][2], P[r][3]);
        __syncthreads();

        // --- O += P V (rank-1 over m, packed f32x2) ---
        #pragma unroll 4
        for (int k = 0; k < 64; k++) {
            ulonglong2 bv = *(const ulonglong2*)&Vs[k*64 + ((4*tx) ^ ((k & 15) << 2))];
            #pragma unroll
            for (int r = 0; r < 4; r++) {
                float p = KP[(4*ty + r)*64 + k];
                unsigned long long ap = pk2(p, p);
                fma2(O2[r][0], ap, bv.x);
                fma2(O2[r][1], ap, bv.y);
            }
        }
    }

    // --- epilogue: normalize and write y[b][c][n] ---
    float Of[4][4];
    #pragma unroll
    for (int r = 0; r < 4; r++) {
        upk2(O2[r][0], Of[r][0], Of[r][1]);
        upk2(O2[r][1], Of[r][2], Of[r][3]);
        float inv = 1.f / li[r];
        #pragma unroll
        for (int j = 0; j < 4; j++) Of[r][j] *= inv;
    }
    float* y = g_y + (size_t)b*64*6400;
    #pragma unroll
    for (int j = 0; j < 4; j++) {
        float4 v = make_float4(Of[0][j], Of[1][j], Of[2][j], Of[3][j]);
        *(float4*)&y[(4*tx + j)*6400 + n0 + 4*ty] = v;
    }
}

// ---------------- kernel 3: W-conv + BN statistics --------------------------
__global__ __launch_bounds__(256) void convW_kernel(
    const float* __restrict__ wW, const float* __restrict__ bW)
{
    __shared__ __align__(16) float ys[64*68];  // ys[c][n]
    __shared__ __align__(16) float ws[64*68];  // ws[c][o]
    __shared__ float ssum[64], ssq[64];
    const int b  = blockIdx.y;
    const int n0 = blockIdx.x * 64;
    const int t  = threadIdx.x;
    const int tx = t & 15, ty = t >> 4;

    const float* yb = g_y + (size_t)b*64*6400;
    for (int i = t; i < 4096; i += 256) {
        int c = i >> 6, n = i & 63;
        ys[c*68 + n] = yb[c*6400 + n0 + n];
    }
    for (int i = t; i < 4096; i += 256) {
        int o = i >> 6, c = i & 63;
        ws[c*68 + o] = wW[i];
    }
    if (t < 64) { ssum[t] = 0.f; ssq[t] = 0.f; }
    __syncthreads();

    float acc[4][4];
    #pragma unroll
    for (int j = 0; j < 4; j++) {
        float bb = bW[4*tx + j];
        #pragma unroll
        for (int r = 0; r < 4; r++) acc[r][j] = bb;
    }
    #pragma unroll 4
    for (int c = 0; c < 64; c++) {
        float4 a  = *(const float4*)&ys[c*68 + 4*ty];
        float4 w4 = *(const float4*)&ws[c*68 + 4*tx];
        acc[0][0] += a.x*w4.x; acc[0][1] += a.x*w4.y; acc[0][2] += a.x*w4.z; acc[0][3] += a.x*w4.w;
        acc[1][0] += a.y*w4.x; acc[1][1] += a.y*w4.y; acc[1][2] += a.y*w4.z; acc[1][3] += a.y*w4.w;
        acc[2][0] += a.z*w4.x; acc[2][1] += a.z*w4.y; acc[2][2] += a.z*w4.z; acc[2][3] += a.z*w4.w;
        acc[3][0] += a.w*w4.x; acc[3][1] += a.w*w4.y; acc[3][2] += a.w*w4.z; acc[3][3] += a.w*w4.w;
    }
    float* dst = g_Wy + (size_t)b*64*6400;
    #pragma unroll
    for (int j = 0; j < 4; j++) {
        float4 v = make_float4(acc[0][j], acc[1][j], acc[2][j], acc[3][j]);
        *(float4*)&dst[(4*tx + j)*6400 + n0 + 4*ty] = v;
    }
    #pragma unroll
    for (int j = 0; j < 4; j++) {
        float s = 0.f, q = 0.f;
        #pragma unroll
        for (int r = 0; r < 4; r++) { s += acc[r][j]; q += acc[r][j]*acc[r][j]; }
        atomicAdd(&ssum[4*tx + j], s);
        atomicAdd(&ssq [4*tx + j], q);
    }
    __syncthreads();
    if (t < 64) {
        atomicAdd(&g_stats[t],      ssum[t]);
        atomicAdd(&g_stats[64 + t], ssq[t]);
    }
}

// ---------------- kernel 4: BN scale/shift ----------------------------------
__global__ void bnstats_kernel(const float* __restrict__ gamma,
                               const float* __restrict__ beta)
{
    int c = threadIdx.x;
    const float invN = 1.f / (float)(B_ * N_);
    float mean = g_stats[c] * invN;
    float var  = g_stats[64 + c] * invN - mean*mean;
    float sc   = gamma[c] * rsqrtf(var + 1e-5f);
    g_sc[c]      = sc;
    g_sc[64 + c] = beta[c] - mean*sc;
}

// ---------------- kernel 5: BN apply + residual ------------------------------
__global__ __launch_bounds__(256) void out_kernel(const float* __restrict__ x,
                                                  float* __restrict__ out)
{
    int i   = blockIdx.x * 256 + threadIdx.x;  // float4 index
    int idx = i * 4;
    int c   = (idx / 6400) & 63;
    float4 wy = *(const float4*)&g_Wy[idx];
    float4 xv = *(const float4*)&x[idx];
    float sc = g_sc[c], sh = g_sc[64 + c];
    float4 o;
    o.x = wy.x*sc + sh + xv.x;
    o.y = wy.y*sc + sh + xv.y;
    o.z = wy.z*sc + sh + xv.z;
    o.w = wy.w*sc + sh + xv.w;
    *(float4*)&out[idx] = o;
}

// ---------------- launch ------------------------------------------------------
extern "C" void kernel_launch(void* const* d_in, const int* in_sizes, int n_in,
                              void* d_out, int out_size)
{
    const float* x     = (const float*)d_in[0];
    const float* wt    = (const float*)d_in[1];
    const float* bt    = (const float*)d_in[2];
    const float* wp    = (const float*)d_in[3];
    const float* bp    = (const float*)d_in[4];
    const float* wg    = (const float*)d_in[5];
    const float* bg    = (const float*)d_in[6];
    const float* wW    = (const float*)d_in[7];
    const float* bW    = (const float*)d_in[8];
    const float* gamma = (const float*)d_in[9];
    const float* beta  = (const float*)d_in[10];

    dim3 grid(NTILES, B_);
    proj3_kernel <<<grid, 256>>>(x, wt, bt, wp, bp, wg, bg);
    flash_kernel <<<grid, 256>>>();
    convW_kernel <<<grid, 256>>>(wW, bW);
    bnstats_kernel<<<1, 64>>>(gamma, beta);
    out_kernel   <<<(B_*C_*N_)/4/256, 256>>>(x, (float*)d_out);
}